// round 7
// baseline (speedup 1.0000x reference)
#include <cuda_runtime.h>
#include <cuda_bf16.h>
#include <cstdint>

#define Bdim 8
#define Wdim 4096
#define Rdim 128
#define Ddim 128
#define BLK  128
#define NBLK 32

// ---------------------------------------------------------------------------
// Scratch (__device__ globals; allocation-free rule)
// ---------------------------------------------------------------------------
__device__ float g_ptab[129 * 128];   // ptab[i*128+r] = gamma_r^i
__device__ float g_ntab[128 * 128];   // ntab[j*128+r] = gamma_r^{-j}
__device__ float g_U[Bdim * NBLK * Ddim * Rdim];     // Ut layout [d][r]
__device__ float g_S[Bdim * NBLK * Ddim * Rdim];     // St layout [d][r]

// ---------------------------------------------------------------------------
// SMEM: 4 bf16 tiles, 128 rows x 136 halves (272B/row, conflict-free ldmatrix)
// ---------------------------------------------------------------------------
#define TROWB   272
#define TBYTES  (128 * TROWB)          // 34816
#define SMEM_TOTAL (4 * TBYTES)        // 139264
#define NTHR 512

__device__ __forceinline__ uint32_t smem_u32(const void* p) {
    uint32_t a;
    asm("{ .reg .u64 t; cvta.to.shared.u64 t, %1; cvt.u32.u64 %0, t; }" : "=r"(a) : "l"(p));
    return a;
}

__device__ __forceinline__ void split1(float a, unsigned short& h, unsigned short& l) {
    __nv_bfloat16 hb = __float2bfloat16(a);
    float rem = a - __bfloat162float(hb);
    __nv_bfloat16 lb = __float2bfloat16(rem);
    h = *(unsigned short*)&hb;
    l = *(unsigned short*)&lb;
}
__device__ __forceinline__ unsigned long long pack4(unsigned short a, unsigned short b,
                                                    unsigned short c, unsigned short d) {
    return (unsigned long long)a | ((unsigned long long)b << 16)
         | ((unsigned long long)c << 32) | ((unsigned long long)d << 48);
}

// ---------------------------------------------------------------------------
// Staging (512 threads): nat dst[m][c] = src[m][c] * wt[(m+wrofs)][c]
// ---------------------------------------------------------------------------
__device__ __forceinline__ void stage_nat(const float* __restrict__ src,
                                          const float* __restrict__ wt, int wrofs,
                                          char* hiT, char* loT, int tid) {
#pragma unroll
    for (int it = 0; it < 8; it++) {
        int t = tid + it * NTHR;
        int row = t >> 5, c4 = (t & 31) << 2;
        float4 v = *(const float4*)(src + row * 128 + c4);
        if (wt) {
            float4 w = *(const float4*)(wt + (row + wrofs) * 128 + c4);
            v.x *= w.x; v.y *= w.y; v.z *= w.z; v.w *= w.w;
        }
        unsigned short h[4], l[4];
        split1(v.x, h[0], l[0]); split1(v.y, h[1], l[1]);
        split1(v.z, h[2], l[2]); split1(v.w, h[3], l[3]);
        int off = row * TROWB + c4 * 2;
        *(unsigned long long*)(hiT + off) = pack4(h[0], h[1], h[2], h[3]);
        *(unsigned long long*)(loT + off) = pack4(l[0], l[1], l[2], l[3]);
    }
}

// tr: dst[c][j] = src[j][c] * (useW ? ptab[(127-j)*128+c] : 1)
__device__ __forceinline__ void stage_tr(const float* __restrict__ src, bool useW,
                                         char* hiT, char* loT, int tid) {
#pragma unroll
    for (int it = 0; it < 2; it++) {
        int t = tid + it * NTHR;
        int j0 = (t >> 5) << 2, c0 = (t & 31) << 2;
        unsigned short hs[4][4], ls[4][4];    // [src row x][src col u]
#pragma unroll
        for (int x = 0; x < 4; x++) {
            float4 v = *(const float4*)(src + (j0 + x) * 128 + c0);
            if (useW) {
                float4 w = *(const float4*)(g_ptab + (127 - (j0 + x)) * 128 + c0);
                v.x *= w.x; v.y *= w.y; v.z *= w.z; v.w *= w.w;
            }
            split1(v.x, hs[x][0], ls[x][0]); split1(v.y, hs[x][1], ls[x][1]);
            split1(v.z, hs[x][2], ls[x][2]); split1(v.w, hs[x][3], ls[x][3]);
        }
#pragma unroll
        for (int u = 0; u < 4; u++) {
            int off = (c0 + u) * TROWB + j0 * 2;
            *(unsigned long long*)(hiT + off) = pack4(hs[0][u], hs[1][u], hs[2][u], hs[3][u]);
            *(unsigned long long*)(loT + off) = pack4(ls[0][u], ls[1][u], ls[2][u], ls[3][u]);
        }
    }
}

// ---------------------------------------------------------------------------
// mma.sync core: 16 warps, warp tile 32x32 (acc[2][4][4] = 32 floats)
// ---------------------------------------------------------------------------
__device__ __forceinline__ void ldsm_x4(uint32_t addr, uint32_t& r0, uint32_t& r1,
                                        uint32_t& r2, uint32_t& r3) {
    asm volatile("ldmatrix.sync.aligned.m8n8.x4.shared.b16 {%0,%1,%2,%3}, [%4];"
                 : "=r"(r0), "=r"(r1), "=r"(r2), "=r"(r3) : "r"(addr));
}
__device__ __forceinline__ void mma16816(float* c, uint32_t a0, uint32_t a1,
                                         uint32_t a2, uint32_t a3,
                                         uint32_t b0, uint32_t b1) {
    asm volatile("mma.sync.aligned.m16n8k16.row.col.f32.bf16.bf16.f32 "
                 "{%0,%1,%2,%3}, {%4,%5,%6,%7}, {%8,%9}, {%0,%1,%2,%3};"
                 : "+f"(c[0]), "+f"(c[1]), "+f"(c[2]), "+f"(c[3])
                 : "r"(a0), "r"(a1), "r"(a2), "r"(a3), "r"(b0), "r"(b1));
}

__device__ __forceinline__ void gemm_prod(uint32_t aT, uint32_t bT,
                                          int m0, int n0, int lane,
                                          float acc[2][4][4]) {
    int r = lane & 7, sub = lane >> 3;
    int aRow = (sub & 1) * 8 + r, aK = (sub >> 1) * 8;
    int bRow = (sub >> 1) * 8 + r, bK = (sub & 1) * 8;
#pragma unroll
    for (int ks = 0; ks < 8; ks++) {
        int k0 = ks * 16;
        uint32_t a[2][4];
#pragma unroll
        for (int am = 0; am < 2; am++) {
            uint32_t addr = aT + (uint32_t)((m0 + am * 16 + aRow) * TROWB + (k0 + aK) * 2);
            ldsm_x4(addr, a[am][0], a[am][1], a[am][2], a[am][3]);
        }
#pragma unroll
        for (int g = 0; g < 2; g++) {
            uint32_t q0, q1, q2, q3;
            uint32_t addr = bT + (uint32_t)((n0 + g * 16 + bRow) * TROWB + (k0 + bK) * 2);
            ldsm_x4(addr, q0, q1, q2, q3);
#pragma unroll
            for (int am = 0; am < 2; am++) {
                mma16816(acc[am][g * 2 + 0], a[am][0], a[am][1], a[am][2], a[am][3], q0, q1);
                mma16816(acc[am][g * 2 + 1], a[am][0], a[am][1], a[am][2], a[am][3], q2, q3);
            }
        }
    }
}

// bf16x3: hi*hi + hi*lo + lo*hi
__device__ __forceinline__ void gemm3(char* smem, int m0, int n0, int lane,
                                      float acc[2][4][4]) {
    uint32_t AHI = smem_u32(smem);
    uint32_t ALO = AHI + TBYTES;
    uint32_t BHI = AHI + 2 * TBYTES;
    uint32_t BLO = AHI + 3 * TBYTES;
    gemm_prod(AHI, BHI, m0, n0, lane, acc);
    gemm_prod(AHI, BLO, m0, n0, lane, acc);
    gemm_prod(ALO, BHI, m0, n0, lane, acc);
}

__device__ __forceinline__ void zero_acc(float acc[2][4][4]) {
#pragma unroll
    for (int am = 0; am < 2; am++)
#pragma unroll
        for (int g = 0; g < 4; g++)
#pragma unroll
            for (int e = 0; e < 4; e++) acc[am][g][e] = 0.f;
}

// Epilogue: write fragments (optionally accumulate onto existing dst)
__device__ __forceinline__ void epilogue(float acc[2][4][4], float* __restrict__ dst,
                                         bool addOld, int m0, int n0, int lane) {
    int t4 = lane >> 2, tp2 = (lane & 3) * 2;
#pragma unroll
    for (int am = 0; am < 2; am++) {
#pragma unroll
        for (int g = 0; g < 4; g++) {
            int col = n0 + g * 8 + tp2;
            int row0 = m0 + am * 16 + t4;
            float c0 = acc[am][g][0], c1 = acc[am][g][1];
            float c2 = acc[am][g][2], c3 = acc[am][g][3];
            if (addOld) {
                float2 p0 = *(float2*)(dst + row0 * 128 + col);
                float2 p1 = *(float2*)(dst + (row0 + 8) * 128 + col);
                c0 += p0.x; c1 += p0.y; c2 += p1.x; c3 += p1.y;
            }
            *(float2*)(dst + row0 * 128 + col)       = make_float2(c0, c1);
            *(float2*)(dst + (row0 + 8) * 128 + col) = make_float2(c2, c3);
        }
    }
}

// Write masked A-fragments directly into SMEM as bf16 hi/lo (skip gmem)
__device__ __forceinline__ void frag_to_smem_masked(float acc[2][4][4],
                                                    char* hiT, char* loT,
                                                    int m0, int n0, int lane) {
    int t4 = lane >> 2, tp2 = (lane & 3) * 2;
#pragma unroll
    for (int am = 0; am < 2; am++) {
#pragma unroll
        for (int g = 0; g < 4; g++) {
            int col = n0 + g * 8 + tp2;
            int row0 = m0 + am * 16 + t4;
            float c0 = acc[am][g][0], c1 = acc[am][g][1];
            float c2 = acc[am][g][2], c3 = acc[am][g][3];
            if (row0 < col)         c0 = 0.f;
            if (row0 < col + 1)     c1 = 0.f;
            if (row0 + 8 < col)     c2 = 0.f;
            if (row0 + 8 < col + 1) c3 = 0.f;
            unsigned short h0, l0, h1, l1;
            split1(c0, h0, l0); split1(c1, h1, l1);
            *(uint32_t*)(hiT + row0 * TROWB + col * 2) = (uint32_t)h0 | ((uint32_t)h1 << 16);
            *(uint32_t*)(loT + row0 * TROWB + col * 2) = (uint32_t)l0 | ((uint32_t)l1 << 16);
            split1(c2, h0, l0); split1(c3, h1, l1);
            *(uint32_t*)(hiT + (row0 + 8) * TROWB + col * 2) = (uint32_t)h0 | ((uint32_t)h1 << 16);
            *(uint32_t*)(loT + (row0 + 8) * TROWB + col * 2) = (uint32_t)l0 | ((uint32_t)l1 << 16);
        }
    }
}

// ---------------------------------------------------------------------------
// Power tables
// ---------------------------------------------------------------------------
__global__ void pow_kernel(const float* __restrict__ gamma) {
    int r = threadIdx.x, row = blockIdx.x;
    float lg = logf(gamma[r]);
    if (row < 129) g_ptab[row * 128 + r] = expf((float)row * lg);
    else           g_ntab[(row - 129) * 128 + r] = expf(-(float)(row - 129) * lg);
}

// ---------------------------------------------------------------------------
// Phase 1:
//  z=0: A = mask((QΓ)(KΓ')^T) held in regs -> SMEM bf16 -> partial out = A @ H
//  z=1: Ut[d,r] = sum_j h[j,d] * (k[j,r] g^(127-j))
// ---------------------------------------------------------------------------
__global__ __launch_bounds__(NTHR) void matAU_kernel(const float* __restrict__ q,
                                                     const float* __restrict__ k,
                                                     const float* __restrict__ h,
                                                     float* __restrict__ out) {
    extern __shared__ __align__(16) char smem[];
    int n = blockIdx.x, b = blockIdx.y;
    int tid = threadIdx.x, wid = tid >> 5, lane = tid & 31;
    int m0 = (wid & 3) * 32, n0 = (wid >> 2) * 32;

    const int in_base = (b * Wdim + n * BLK) * Rdim;
    float acc[2][4][4];
    zero_acc(acc);

    if (blockIdx.z == 0) {
        // --- step 1: A fragments ---
        stage_nat(q + in_base, g_ptab, 0, smem, smem + TBYTES, tid);
        stage_nat(k + in_base, g_ntab, 0, smem + 2 * TBYTES, smem + 3 * TBYTES, tid);
        __syncthreads();
        gemm3(smem, m0, n0, lane, acc);
        __syncthreads();   // all reads of tiles done before overwrite

        // --- step 2: masked A -> SMEM bf16; stage H^T; partial out = A @ H ---
        frag_to_smem_masked(acc, smem, smem + TBYTES, m0, n0, lane);
        stage_tr(h + in_base, false, smem + 2 * TBYTES, smem + 3 * TBYTES, tid);
        __syncthreads();
        zero_acc(acc);
        gemm3(smem, m0, n0, lane, acc);
        epilogue(acc, out + (b * Wdim + n * BLK) * Ddim, false, m0, n0, lane);
    } else {
        // Ut[d][r]
        stage_tr(h + in_base, false, smem, smem + TBYTES, tid);                  // A[d][j]
        stage_tr(k + in_base, true,  smem + 2 * TBYTES, smem + 3 * TBYTES, tid); // B[r][j]
        __syncthreads();
        gemm3(smem, m0, n0, lane, acc);
        epilogue(acc, g_U + (b * NBLK + n) * (Ddim * Rdim), false, m0, n0, lane);
    }
}

// ---------------------------------------------------------------------------
// Phase 2: prefix scan on [d][r] state, MLP-32 preload
// ---------------------------------------------------------------------------
__global__ void scan_kernel() {
    int gid = blockIdx.x * 256 + threadIdx.x;   // 131072
    int b = gid >> 14, dr = gid & 16383, r = dr & 127;
    float gdec = g_ptab[128 * 128 + r];         // gamma_r^128
    int base = b * NBLK * 16384 + dr;
    float u[NBLK];
#pragma unroll
    for (int nn = 0; nn < NBLK; nn++) u[nn] = g_U[base + nn * 16384];
    float s = 0.f;
#pragma unroll
    for (int nn = 0; nn < NBLK; nn++) {
        g_S[base + nn * 16384] = s;
        s = fmaf(s, gdec, u[nn]);
    }
}

// ---------------------------------------------------------------------------
// Phase 3: out += (Q*g^(i+1)) @ St
// ---------------------------------------------------------------------------
__global__ __launch_bounds__(NTHR) void out_kernel(const float* __restrict__ q,
                                                   float* __restrict__ out) {
    extern __shared__ __align__(16) char smem[];
    int n = blockIdx.x, b = blockIdx.y;
    int tid = threadIdx.x, wid = tid >> 5, lane = tid & 31;
    int m0 = (wid & 3) * 32, n0 = (wid >> 2) * 32;

    const float* Sblk = g_S + (b * NBLK + n) * (Ddim * Rdim);
    const int qbase = (b * Wdim + n * BLK) * Rdim;

    stage_nat(q + qbase, g_ptab, 1, smem, smem + TBYTES, tid);
    stage_nat(Sblk, (const float*)0, 0, smem + 2 * TBYTES, smem + 3 * TBYTES, tid);
    __syncthreads();

    float acc[2][4][4];
    zero_acc(acc);
    gemm3(smem, m0, n0, lane, acc);
    epilogue(acc, out + (b * Wdim + n * BLK) * Ddim, true, m0, n0, lane);
}

// ---------------------------------------------------------------------------
extern "C" void kernel_launch(void* const* d_in, const int* in_sizes, int n_in,
                              void* d_out, int out_size) {
    const float* q     = (const float*)d_in[0];
    const float* k     = (const float*)d_in[1];
    const float* h     = (const float*)d_in[2];
    const float* gamma = (const float*)d_in[3];
    float* out = (float*)d_out;

    cudaFuncSetAttribute(matAU_kernel, cudaFuncAttributeMaxDynamicSharedMemorySize, SMEM_TOTAL);
    cudaFuncSetAttribute(out_kernel,   cudaFuncAttributeMaxDynamicSharedMemorySize, SMEM_TOTAL);

    pow_kernel<<<257, 128>>>(gamma);
    matAU_kernel<<<dim3(NBLK, Bdim, 2), NTHR, SMEM_TOTAL>>>(q, k, h, out);
    scan_kernel<<<512, 256>>>();
    out_kernel<<<dim3(NBLK, Bdim), NTHR, SMEM_TOTAL>>>(q, out);
}

// round 8
// speedup vs baseline: 1.2562x; 1.2562x over previous
#include <cuda_runtime.h>
#include <cuda_bf16.h>
#include <cstdint>

#define Bdim 8
#define Wdim 4096
#define Rdim 128
#define Ddim 128
#define BLK  128
#define NBLK 32

// ---------------------------------------------------------------------------
// Scratch (__device__ globals; allocation-free rule)
// ---------------------------------------------------------------------------
__device__ float g_ptab[129 * 128];   // ptab[i*128+r] = gamma_r^i
__device__ float g_ntab[128 * 128];   // ntab[j*128+r] = gamma_r^{-j}
__device__ float g_A[Bdim * NBLK * BLK * BLK];       // masked A[i][j]
__device__ float g_U[Bdim * NBLK * Ddim * Rdim];     // Ut layout [d][r]
__device__ float g_S[Bdim * NBLK * Ddim * Rdim];     // St layout [d][r]

// ---------------------------------------------------------------------------
// SMEM: 4 bf16 chunk tiles, 128 rows x 72 halves (144B/row, k-chunk = 64)
// ---------------------------------------------------------------------------
#define CROWB   144
#define CBYTES  (128 * CROWB)              // 18432
#define SMEM_TOTAL (4 * CBYTES)            // 73728  -> 2 CTAs/SM
#define NTHR 256

__device__ __forceinline__ uint32_t smem_u32(const void* p) {
    uint32_t a;
    asm("{ .reg .u64 t; cvta.to.shared.u64 t, %1; cvt.u32.u64 %0, t; }" : "=r"(a) : "l"(p));
    return a;
}

__device__ __forceinline__ void split1(float a, unsigned short& h, unsigned short& l) {
    __nv_bfloat16 hb = __float2bfloat16(a);
    float rem = a - __bfloat162float(hb);
    __nv_bfloat16 lb = __float2bfloat16(rem);
    h = *(unsigned short*)&hb;
    l = *(unsigned short*)&lb;
}
__device__ __forceinline__ unsigned long long pack4(unsigned short a, unsigned short b,
                                                    unsigned short c, unsigned short d) {
    return (unsigned long long)a | ((unsigned long long)b << 16)
         | ((unsigned long long)c << 32) | ((unsigned long long)d << 48);
}

// ---------------------------------------------------------------------------
// Chunked staging (256 threads, 64-column chunk starting at kc)
// nat: dst[m][c-kc] = src[m][c] * wt[(m+wrofs)][c]
// ---------------------------------------------------------------------------
__device__ __forceinline__ void stage_nat_c(const float* __restrict__ src,
                                            const float* __restrict__ wt, int wrofs,
                                            int kc, char* hiT, char* loT, int tid) {
#pragma unroll
    for (int it = 0; it < 8; it++) {
        int t = tid + it * NTHR;            // 0..2047
        int row = t >> 4;                   // 0..127
        int c4  = (t & 15) << 2;            // 0..60
        float4 v = *(const float4*)(src + row * 128 + kc + c4);
        if (wt) {
            float4 w = *(const float4*)(wt + (row + wrofs) * 128 + kc + c4);
            v.x *= w.x; v.y *= w.y; v.z *= w.z; v.w *= w.w;
        }
        unsigned short h[4], l[4];
        split1(v.x, h[0], l[0]); split1(v.y, h[1], l[1]);
        split1(v.z, h[2], l[2]); split1(v.w, h[3], l[3]);
        int off = row * CROWB + c4 * 2;
        *(unsigned long long*)(hiT + off) = pack4(h[0], h[1], h[2], h[3]);
        *(unsigned long long*)(loT + off) = pack4(l[0], l[1], l[2], l[3]);
    }
}

// tr: dst[c][j-jc] = src[j][c] * (useW ? ptab[(127-j)*128+c] : 1),  j in [jc,jc+64)
__device__ __forceinline__ void stage_tr_c(const float* __restrict__ src, bool useW,
                                           int jc, char* hiT, char* loT, int tid) {
#pragma unroll
    for (int it = 0; it < 2; it++) {
        int t = tid + it * NTHR;            // 0..511
        int jblk = t >> 5;                  // 0..15
        int c0   = (t & 31) << 2;           // 0..124
        int j0   = jc + jblk * 4;
        unsigned short hs[4][4], ls[4][4];  // [src row x][src col u]
#pragma unroll
        for (int x = 0; x < 4; x++) {
            float4 v = *(const float4*)(src + (j0 + x) * 128 + c0);
            if (useW) {
                float4 w = *(const float4*)(g_ptab + (127 - (j0 + x)) * 128 + c0);
                v.x *= w.x; v.y *= w.y; v.z *= w.z; v.w *= w.w;
            }
            split1(v.x, hs[x][0], ls[x][0]); split1(v.y, hs[x][1], ls[x][1]);
            split1(v.z, hs[x][2], ls[x][2]); split1(v.w, hs[x][3], ls[x][3]);
        }
#pragma unroll
        for (int u = 0; u < 4; u++) {
            int off = (c0 + u) * CROWB + jblk * 8;
            *(unsigned long long*)(hiT + off) = pack4(hs[0][u], hs[1][u], hs[2][u], hs[3][u]);
            *(unsigned long long*)(loT + off) = pack4(ls[0][u], ls[1][u], ls[2][u], ls[3][u]);
        }
    }
}

// ---------------------------------------------------------------------------
// mma.sync core: 8 warps, warp tile 32x64 (acc[2][8][4] = 64 floats)
// Fused bf16x3 per k-step: hi*hi + hi*lo + lo*hi into the same acc
// ---------------------------------------------------------------------------
__device__ __forceinline__ void ldsm_x4(uint32_t addr, uint32_t& r0, uint32_t& r1,
                                        uint32_t& r2, uint32_t& r3) {
    asm volatile("ldmatrix.sync.aligned.m8n8.x4.shared.b16 {%0,%1,%2,%3}, [%4];"
                 : "=r"(r0), "=r"(r1), "=r"(r2), "=r"(r3) : "r"(addr));
}
__device__ __forceinline__ void mma16816(float* c, const uint32_t a[4],
                                         uint32_t b0, uint32_t b1) {
    asm volatile("mma.sync.aligned.m16n8k16.row.col.f32.bf16.bf16.f32 "
                 "{%0,%1,%2,%3}, {%4,%5,%6,%7}, {%8,%9}, {%0,%1,%2,%3};"
                 : "+f"(c[0]), "+f"(c[1]), "+f"(c[2]), "+f"(c[3])
                 : "r"(a[0]), "r"(a[1]), "r"(a[2]), "r"(a[3]), "r"(b0), "r"(b1));
}

// One 64-k chunk, all 3 products fused. Tiles at smem: AHI|ALO|BHI|BLO.
__device__ __forceinline__ void gemm3_c(char* smem, int m0, int n0, int lane,
                                        float acc[2][8][4]) {
    uint32_t AHI = smem_u32(smem);
    uint32_t ALO = AHI + CBYTES;
    uint32_t BHI = AHI + 2 * CBYTES;
    uint32_t BLO = AHI + 3 * CBYTES;
    int r = lane & 7, sub = lane >> 3;
    int aRow = (sub & 1) * 8 + r, aK = (sub >> 1) * 8;
    int bRow = (sub >> 1) * 8 + r, bK = (sub & 1) * 8;
#pragma unroll
    for (int ks = 0; ks < 4; ks++) {
        int k0 = ks * 16;
        uint32_t ahi[2][4], alo[2][4];
#pragma unroll
        for (int am = 0; am < 2; am++) {
            uint32_t base = (uint32_t)((m0 + am * 16 + aRow) * CROWB + (k0 + aK) * 2);
            ldsm_x4(AHI + base, ahi[am][0], ahi[am][1], ahi[am][2], ahi[am][3]);
            ldsm_x4(ALO + base, alo[am][0], alo[am][1], alo[am][2], alo[am][3]);
        }
#pragma unroll
        for (int g = 0; g < 4; g++) {
            uint32_t base = (uint32_t)((n0 + g * 16 + bRow) * CROWB + (k0 + bK) * 2);
            uint32_t bh0, bh1, bh2, bh3, bl0, bl1, bl2, bl3;
            ldsm_x4(BHI + base, bh0, bh1, bh2, bh3);
            ldsm_x4(BLO + base, bl0, bl1, bl2, bl3);
#pragma unroll
            for (int am = 0; am < 2; am++) {
                mma16816(acc[am][g * 2 + 0], ahi[am], bh0, bh1);
                mma16816(acc[am][g * 2 + 1], ahi[am], bh2, bh3);
                mma16816(acc[am][g * 2 + 0], ahi[am], bl0, bl1);
                mma16816(acc[am][g * 2 + 1], ahi[am], bl2, bl3);
                mma16816(acc[am][g * 2 + 0], alo[am], bh0, bh1);
                mma16816(acc[am][g * 2 + 1], alo[am], bh2, bh3);
            }
        }
    }
}

__device__ __forceinline__ void zero_acc(float acc[2][8][4]) {
#pragma unroll
    for (int am = 0; am < 2; am++)
#pragma unroll
        for (int g = 0; g < 8; g++)
#pragma unroll
            for (int e = 0; e < 4; e++) acc[am][g][e] = 0.f;
}

// Epilogue: write fragments; optional causal mask (zero where i<j)
__device__ __forceinline__ void epilogue(float acc[2][8][4], float* __restrict__ dst,
                                         bool mask, int m0, int n0, int lane) {
    int t4 = lane >> 2, tp2 = (lane & 3) * 2;
#pragma unroll
    for (int am = 0; am < 2; am++) {
#pragma unroll
        for (int g = 0; g < 8; g++) {
            int col = n0 + g * 8 + tp2;
            int row0 = m0 + am * 16 + t4;
            float c0 = acc[am][g][0], c1 = acc[am][g][1];
            float c2 = acc[am][g][2], c3 = acc[am][g][3];
            if (mask) {
                if (row0 < col)         c0 = 0.f;
                if (row0 < col + 1)     c1 = 0.f;
                if (row0 + 8 < col)     c2 = 0.f;
                if (row0 + 8 < col + 1) c3 = 0.f;
            }
            *(float2*)(dst + row0 * 128 + col)       = make_float2(c0, c1);
            *(float2*)(dst + (row0 + 8) * 128 + col) = make_float2(c2, c3);
        }
    }
}

// ---------------------------------------------------------------------------
// Power tables
// ---------------------------------------------------------------------------
__global__ void pow_kernel(const float* __restrict__ gamma) {
    int r = threadIdx.x, row = blockIdx.x;
    float lg = logf(gamma[r]);
    if (row < 129) g_ptab[row * 128 + r] = expf((float)row * lg);
    else           g_ntab[(row - 129) * 128 + r] = expf(-(float)(row - 129) * lg);
}

// ---------------------------------------------------------------------------
// Phase 1 (z=0): A[i,j] = mask * (QΓ)(KΓ')^T ; (z=1): Ut[d,r]
// ---------------------------------------------------------------------------
__global__ __launch_bounds__(NTHR, 2) void matAU_kernel(const float* __restrict__ q,
                                                        const float* __restrict__ k,
                                                        const float* __restrict__ h) {
    extern __shared__ __align__(16) char smem[];
    int n = blockIdx.x, b = blockIdx.y;
    int tid = threadIdx.x, wid = tid >> 5, lane = tid & 31;
    int m0 = (wid & 3) * 32, n0 = (wid >> 2) * 64;

    const int in_base = (b * Wdim + n * BLK) * Rdim;
    float acc[2][8][4];
    zero_acc(acc);

    if (blockIdx.z == 0) {
#pragma unroll
        for (int kc = 0; kc < 128; kc += 64) {
            stage_nat_c(q + in_base, g_ptab, 0, kc, smem, smem + CBYTES, tid);
            stage_nat_c(k + in_base, g_ntab, 0, kc, smem + 2 * CBYTES, smem + 3 * CBYTES, tid);
            __syncthreads();
            gemm3_c(smem, m0, n0, lane, acc);
            __syncthreads();
        }
        epilogue(acc, g_A + (b * NBLK + n) * (BLK * BLK), true, m0, n0, lane);
    } else {
#pragma unroll
        for (int jc = 0; jc < 128; jc += 64) {
            stage_tr_c(h + in_base, false, jc, smem, smem + CBYTES, tid);
            stage_tr_c(k + in_base, true,  jc, smem + 2 * CBYTES, smem + 3 * CBYTES, tid);
            __syncthreads();
            gemm3_c(smem, m0, n0, lane, acc);
            __syncthreads();
        }
        epilogue(acc, g_U + (b * NBLK + n) * (Ddim * Rdim), false, m0, n0, lane);
    }
}

// ---------------------------------------------------------------------------
// Phase 2: prefix scan on [d][r] state, MLP-32 preload
// ---------------------------------------------------------------------------
__global__ void scan_kernel() {
    int gid = blockIdx.x * 256 + threadIdx.x;   // 131072
    int b = gid >> 14, dr = gid & 16383, r = dr & 127;
    float gdec = g_ptab[128 * 128 + r];         // gamma_r^128
    int base = b * NBLK * 16384 + dr;
    float u[NBLK];
#pragma unroll
    for (int nn = 0; nn < NBLK; nn++) u[nn] = g_U[base + nn * 16384];
    float s = 0.f;
#pragma unroll
    for (int nn = 0; nn < NBLK; nn++) {
        g_S[base + nn * 16384] = s;
        s = fmaf(s, gdec, u[nn]);
    }
}

// ---------------------------------------------------------------------------
// Phase 3: out = A @ H + (Q*g^(i+1)) @ St  (acc carried across both parts)
// ---------------------------------------------------------------------------
__global__ __launch_bounds__(NTHR, 2) void out_kernel(const float* __restrict__ q,
                                                      const float* __restrict__ h,
                                                      float* __restrict__ out) {
    extern __shared__ __align__(16) char smem[];
    int n = blockIdx.x, b = blockIdx.y;
    int tid = threadIdx.x, wid = tid >> 5, lane = tid & 31;
    int m0 = (wid & 3) * 32, n0 = (wid >> 2) * 64;

    const float* Ablk = g_A + (b * NBLK + n) * (BLK * BLK);
    const float* Sblk = g_S + (b * NBLK + n) * (Ddim * Rdim);
    const int hbase = (b * Wdim + n * BLK) * Ddim;
    const int qbase = (b * Wdim + n * BLK) * Rdim;

    float acc[2][8][4];
    zero_acc(acc);

    // part 1: A @ H  (A nat, contraction j chunked; B = h^T)
#pragma unroll
    for (int jc = 0; jc < 128; jc += 64) {
        stage_nat_c(Ablk, (const float*)0, 0, jc, smem, smem + CBYTES, tid);
        stage_tr_c(h + hbase, false, jc, smem + 2 * CBYTES, smem + 3 * CBYTES, tid);
        __syncthreads();
        gemm3_c(smem, m0, n0, lane, acc);
        __syncthreads();
    }
    // part 2: (Q*g^(i+1)) @ St  (both nat, contraction r chunked)
#pragma unroll
    for (int rc = 0; rc < 128; rc += 64) {
        stage_nat_c(q + qbase, g_ptab, 1, rc, smem, smem + CBYTES, tid);
        stage_nat_c(Sblk, (const float*)0, 0, rc, smem + 2 * CBYTES, smem + 3 * CBYTES, tid);
        __syncthreads();
        gemm3_c(smem, m0, n0, lane, acc);
        __syncthreads();
    }

    epilogue(acc, out + (b * Wdim + n * BLK) * Ddim, false, m0, n0, lane);
}

// ---------------------------------------------------------------------------
extern "C" void kernel_launch(void* const* d_in, const int* in_sizes, int n_in,
                              void* d_out, int out_size) {
    const float* q     = (const float*)d_in[0];
    const float* k     = (const float*)d_in[1];
    const float* h     = (const float*)d_in[2];
    const float* gamma = (const float*)d_in[3];
    float* out = (float*)d_out;

    cudaFuncSetAttribute(matAU_kernel, cudaFuncAttributeMaxDynamicSharedMemorySize, SMEM_TOTAL);
    cudaFuncSetAttribute(out_kernel,   cudaFuncAttributeMaxDynamicSharedMemorySize, SMEM_TOTAL);

    pow_kernel<<<257, 128>>>(gamma);
    matAU_kernel<<<dim3(NBLK, Bdim, 2), NTHR, SMEM_TOTAL>>>(q, k, h);
    scan_kernel<<<512, 256>>>();
    out_kernel<<<dim3(NBLK, Bdim), NTHR, SMEM_TOTAL>>>(q, h, out);
}